// round 1
// baseline (speedup 1.0000x reference)
#include <cuda_runtime.h>
#include <math_constants.h>

// Problem constants
#define BSZ 8
#define TT  1024
#define EE  512
#define NH  8
#define NCU 6
#define HDM 64
#define BQ  32

// Scratch (allocation-free rule: __device__ globals)
__device__ float g_Q[BSZ*NH*TT*HDM];
__device__ float g_K[BSZ*NH*TT*HDM];
__device__ float g_V[BSZ*NH*TT*HDM];
__device__ float g_ctx[BSZ*TT*EE];

// ---------------------------------------------------------------------------
// Fused QKV projection: Y = X @ W^T, W row-major [out,in].
// Block tile 64x64, K-step 16, 256 threads, 4x4 micro-tile.
// N-space = 3*512 (wq|wk|wv). Output scattered to [b,h,t,hd].
// ---------------------------------------------------------------------------
__global__ __launch_bounds__(256) void qkv_kernel(
    const float* __restrict__ x, const float* __restrict__ wq,
    const float* __restrict__ wk, const float* __restrict__ wv) {
  __shared__ float Xs[16*68];
  __shared__ float Ws[16*68];
  const int nb = blockIdx.x;           // 0..23
  const int mb = blockIdx.y;           // 0..127
  const int mat = nb >> 3;
  const int n0 = (nb & 7) << 6;
  const int m0 = mb << 6;
  const float* W  = (mat == 0) ? wq : (mat == 1) ? wk : wv;
  float* dst      = (mat == 0) ? g_Q : (mat == 1) ? g_K : g_V;
  const int tid = threadIdx.x;
  const int tx = tid & 15, ty = tid >> 4;
  const int lm = tid >> 2;
  const int lk = (tid & 3) << 2;

  float acc[4][4];
#pragma unroll
  for (int i = 0; i < 4; i++)
#pragma unroll
    for (int j = 0; j < 4; j++) acc[i][j] = 0.f;

  for (int k0 = 0; k0 < EE; k0 += 16) {
    float4 xa = *(const float4*)&x[(m0 + lm)*EE + k0 + lk];
    float4 wa = *(const float4*)&W[(n0 + lm)*EE + k0 + lk];
    __syncthreads();
    Xs[(lk+0)*68 + lm] = xa.x; Xs[(lk+1)*68 + lm] = xa.y;
    Xs[(lk+2)*68 + lm] = xa.z; Xs[(lk+3)*68 + lm] = xa.w;
    Ws[(lk+0)*68 + lm] = wa.x; Ws[(lk+1)*68 + lm] = wa.y;
    Ws[(lk+2)*68 + lm] = wa.z; Ws[(lk+3)*68 + lm] = wa.w;
    __syncthreads();
#pragma unroll
    for (int k = 0; k < 16; k++) {
      float4 a = *(const float4*)&Xs[k*68 + (ty<<2)];
      float4 b = *(const float4*)&Ws[k*68 + (tx<<2)];
      acc[0][0] += a.x*b.x; acc[0][1] += a.x*b.y; acc[0][2] += a.x*b.z; acc[0][3] += a.x*b.w;
      acc[1][0] += a.y*b.x; acc[1][1] += a.y*b.y; acc[1][2] += a.y*b.z; acc[1][3] += a.y*b.w;
      acc[2][0] += a.z*b.x; acc[2][1] += a.z*b.y; acc[2][2] += a.z*b.z; acc[2][3] += a.z*b.w;
      acc[3][0] += a.w*b.x; acc[3][1] += a.w*b.y; acc[3][2] += a.w*b.z; acc[3][3] += a.w*b.w;
    }
  }
  const int n = n0 + (tx << 2);
  const int h = n >> 6, d = n & 63;
#pragma unroll
  for (int ii = 0; ii < 4; ii++) {
    const int m = m0 + (ty << 2) + ii;
    const int b = m >> 10, t = m & 1023;
    float4 v = make_float4(acc[ii][0], acc[ii][1], acc[ii][2], acc[ii][3]);
    *(float4*)&dst[((size_t)((b*NH + h)*TT) + t)*HDM + d] = v;
  }
}

// ---------------------------------------------------------------------------
// Output projection: out = ctx @ wo^T + bo
// ---------------------------------------------------------------------------
__global__ __launch_bounds__(256) void oproj_kernel(
    const float* __restrict__ wo, const float* __restrict__ bo,
    float* __restrict__ out) {
  __shared__ float Xs[16*68];
  __shared__ float Ws[16*68];
  const int n0 = blockIdx.x << 6;
  const int m0 = blockIdx.y << 6;
  const int tid = threadIdx.x;
  const int tx = tid & 15, ty = tid >> 4;
  const int lm = tid >> 2;
  const int lk = (tid & 3) << 2;

  float acc[4][4];
#pragma unroll
  for (int i = 0; i < 4; i++)
#pragma unroll
    for (int j = 0; j < 4; j++) acc[i][j] = 0.f;

  for (int k0 = 0; k0 < EE; k0 += 16) {
    float4 xa = *(const float4*)&g_ctx[(m0 + lm)*EE + k0 + lk];
    float4 wa = *(const float4*)&wo[(n0 + lm)*EE + k0 + lk];
    __syncthreads();
    Xs[(lk+0)*68 + lm] = xa.x; Xs[(lk+1)*68 + lm] = xa.y;
    Xs[(lk+2)*68 + lm] = xa.z; Xs[(lk+3)*68 + lm] = xa.w;
    Ws[(lk+0)*68 + lm] = wa.x; Ws[(lk+1)*68 + lm] = wa.y;
    Ws[(lk+2)*68 + lm] = wa.z; Ws[(lk+3)*68 + lm] = wa.w;
    __syncthreads();
#pragma unroll
    for (int k = 0; k < 16; k++) {
      float4 a = *(const float4*)&Xs[k*68 + (ty<<2)];
      float4 b = *(const float4*)&Ws[k*68 + (tx<<2)];
      acc[0][0] += a.x*b.x; acc[0][1] += a.x*b.y; acc[0][2] += a.x*b.z; acc[0][3] += a.x*b.w;
      acc[1][0] += a.y*b.x; acc[1][1] += a.y*b.y; acc[1][2] += a.y*b.z; acc[1][3] += a.y*b.w;
      acc[2][0] += a.z*b.x; acc[2][1] += a.z*b.y; acc[2][2] += a.z*b.z; acc[2][3] += a.z*b.w;
      acc[3][0] += a.w*b.x; acc[3][1] += a.w*b.y; acc[3][2] += a.w*b.z; acc[3][3] += a.w*b.w;
    }
  }
  const int n = n0 + (tx << 2);
  float4 bv = *(const float4*)&bo[n];
#pragma unroll
  for (int ii = 0; ii < 4; ii++) {
    const int m = m0 + (ty << 2) + ii;
    float4 v = make_float4(acc[ii][0] + bv.x, acc[ii][1] + bv.y,
                           acc[ii][2] + bv.z, acc[ii][3] + bv.w);
    *(float4*)&out[(size_t)m*EE + n] = v;
  }
}

// ---------------------------------------------------------------------------
// Attention: one block per (h, q-tile of 32, b); h fastest for L2 reuse of u.
// Full score rows (32 x 1024) staged in dynamic smem -> exact softmax,
// coalesced attn write, then P@V with V tiles staged in smem.
// scores = QK^T * 8 + ubias (reference DIVIDES by hd^-0.5).
// ---------------------------------------------------------------------------
__global__ __launch_bounds__(256, 1) void attn_kernel(
    const float* __restrict__ u, const unsigned char* __restrict__ umask,
    const float* __restrict__ wu, const float* __restrict__ bu,
    float* __restrict__ attn_out) {
  extern __shared__ float sm[];
  float* S        = sm;            // 32*1024
  float* Qs       = sm + 32768;    // 64*36 (k-major, padded)
  float* KV       = sm + 35072;    // 64*132 (K k-major) / 64*68 (V)
  float* rowscale = sm + 43520;    // 32

  const int h  = blockIdx.x;
  const int qt = blockIdx.y;
  const int b  = blockIdx.z;
  const int tid = threadIdx.x;
  const int bh = b*NH + h;
  const float* Qp = g_Q + (size_t)bh*TT*HDM + (size_t)qt*BQ*HDM;
  const float* Kp = g_K + (size_t)bh*TT*HDM;
  const float* Vp = g_V + (size_t)bh*TT*HDM;

  // --- load Q tile transposed: Qs[k][i], 32x64 ---
#pragma unroll
  for (int r = 0; r < 2; r++) {
    int id = tid + (r << 8);
    int i = id >> 4;
    int k4 = (id & 15) << 2;
    float4 v = *(const float4*)&Qp[i*HDM + k4];
    Qs[(k4+0)*36 + i] = v.x; Qs[(k4+1)*36 + i] = v.y;
    Qs[(k4+2)*36 + i] = v.z; Qs[(k4+3)*36 + i] = v.w;
  }
  float wuh[NCU];
#pragma unroll
  for (int c = 0; c < NCU; c++) wuh[c] = wu[h*NCU + c];
  const float buh = bu[h];

  const int jx = tid & 31;   // 32 j-groups of 4
  const int qy = tid >> 5;   // 8 q-groups of 4

  // --- Phase 1: scores + ubias + mask into S ---
  for (int jt = 0; jt < 8; jt++) {
    const int j0 = jt << 7;  // 128-wide j tile
    __syncthreads();
    // load K tile transposed: KV[k][j], 128 j x 64 k
#pragma unroll
    for (int r = 0; r < 8; r++) {
      int id = tid + (r << 8);
      int j = id >> 4;
      int k4 = (id & 15) << 2;
      float4 v = *(const float4*)&Kp[(size_t)(j0 + j)*HDM + k4];
      KV[(k4+0)*132 + j] = v.x; KV[(k4+1)*132 + j] = v.y;
      KV[(k4+2)*132 + j] = v.z; KV[(k4+3)*132 + j] = v.w;
    }
    __syncthreads();

    float acc[4][4];
#pragma unroll
    for (int i = 0; i < 4; i++)
#pragma unroll
      for (int j = 0; j < 4; j++) acc[i][j] = 0.f;

#pragma unroll 8
    for (int k = 0; k < HDM; k++) {
      float4 a = *(const float4*)&Qs[k*36 + (qy<<2)];
      float4 c = *(const float4*)&KV[k*132 + (jx<<2)];
      acc[0][0] += a.x*c.x; acc[0][1] += a.x*c.y; acc[0][2] += a.x*c.z; acc[0][3] += a.x*c.w;
      acc[1][0] += a.y*c.x; acc[1][1] += a.y*c.y; acc[1][2] += a.y*c.z; acc[1][3] += a.y*c.w;
      acc[2][0] += a.z*c.x; acc[2][1] += a.z*c.y; acc[2][2] += a.z*c.z; acc[2][3] += a.z*c.w;
      acc[3][0] += a.w*c.x; acc[3][1] += a.w*c.y; acc[3][2] += a.w*c.z; acc[3][3] += a.w*c.w;
    }

    // epilogue: *8, + ubias(u,wu,bu), mask -> S
    float4 row[4];
#pragma unroll
    for (int ii = 0; ii < 4; ii++) {
      const int ig = (qt<<5) + (qy<<2) + ii;
      float4 bias = make_float4(buh, buh, buh, buh);
#pragma unroll
      for (int c = 0; c < NCU; c++) {
        const float4 uv = *(const float4*)&u[(((size_t)(b*NCU + c)*TT + ig)<<10) + j0 + (jx<<2)];
        bias.x += wuh[c]*uv.x; bias.y += wuh[c]*uv.y;
        bias.z += wuh[c]*uv.z; bias.w += wuh[c]*uv.w;
      }
      row[ii] = make_float4(acc[ii][0]*8.f + bias.x, acc[ii][1]*8.f + bias.y,
                            acc[ii][2]*8.f + bias.z, acc[ii][3]*8.f + bias.w);
    }
    // mask_t[b,0,i,j] = umask[b, j, i, 0]
    const int ib = (qt<<5) + (qy<<2);
#pragma unroll
    for (int jj = 0; jj < 4; jj++) {
      const int jg = j0 + (jx<<2) + jj;
      uchar4 m4 = *(const uchar4*)&umask[((size_t)b<<20) + ((size_t)jg<<10) + ib];
      if (m4.x) ((float*)&row[0])[jj] = -CUDART_INF_F;
      if (m4.y) ((float*)&row[1])[jj] = -CUDART_INF_F;
      if (m4.z) ((float*)&row[2])[jj] = -CUDART_INF_F;
      if (m4.w) ((float*)&row[3])[jj] = -CUDART_INF_F;
    }
#pragma unroll
    for (int ii = 0; ii < 4; ii++)
      *(float4*)&S[(((qy<<2)+ii)<<10) + j0 + (jx<<2)] = row[ii];
  }
  __syncthreads();

  // --- Phase 2: softmax per row (unnormalized exp in S, 1/sum in rowscale) ---
  {
    const int lane = tid & 31, w = tid >> 5;
#pragma unroll
    for (int rr = 0; rr < 4; rr++) {
      const int r = (w << 2) + rr;
      float4* Sr = (float4*)&S[r << 10];
      float mx = -CUDART_INF_F;
#pragma unroll
      for (int it = 0; it < 8; it++) {
        float4 v = Sr[lane + (it << 5)];
        mx = fmaxf(mx, fmaxf(fmaxf(v.x, v.y), fmaxf(v.z, v.w)));
      }
#pragma unroll
      for (int off = 16; off > 0; off >>= 1)
        mx = fmaxf(mx, __shfl_xor_sync(0xffffffffu, mx, off));
      float sum = 0.f;
#pragma unroll
      for (int it = 0; it < 8; it++) {
        float4 v = Sr[lane + (it << 5)];
        v.x = __expf(v.x - mx); v.y = __expf(v.y - mx);
        v.z = __expf(v.z - mx); v.w = __expf(v.w - mx);
        Sr[lane + (it << 5)] = v;
        sum += v.x + v.y + v.z + v.w;
      }
#pragma unroll
      for (int off = 16; off > 0; off >>= 1)
        sum += __shfl_xor_sync(0xffffffffu, sum, off);
      if (lane == 0) rowscale[r] = 1.f / sum;
    }
  }
  __syncthreads();

  // --- Phase 3a: write attn (normalized), fully coalesced ---
#pragma unroll 4
  for (int r = 0; r < BQ; r++) {
    const float sc = rowscale[r];
    float4 v = ((const float4*)&S[r << 10])[tid];
    v.x *= sc; v.y *= sc; v.z *= sc; v.w *= sc;
    const size_t ig = (size_t)bh*TT + (qt<<5) + r;
    ((float4*)&attn_out[ig << 10])[tid] = v;
  }

  // --- Phase 3b: ctx = P @ V ---
  {
    const int dx = tid & 7, q2 = tid >> 3;
    float accv[8];
#pragma unroll
    for (int i = 0; i < 8; i++) accv[i] = 0.f;
    for (int vt = 0; vt < 16; vt++) {
      __syncthreads();
#pragma unroll
      for (int r = 0; r < 4; r++) {
        int id = tid + (r << 8);
        int j = id >> 4;
        int d4 = (id & 15) << 2;
        *(float4*)&KV[j*68 + d4] = *(const float4*)&Vp[(size_t)((vt<<6) + j)*HDM + d4];
      }
      __syncthreads();
      const float* Srow = &S[(q2 << 10) + (vt << 6)];
#pragma unroll 8
      for (int j = 0; j < 64; j++) {
        const float p = Srow[j];
        float4 v0 = *(const float4*)&KV[j*68 + (dx<<3)];
        float4 v1 = *(const float4*)&KV[j*68 + (dx<<3) + 4];
        accv[0] += p*v0.x; accv[1] += p*v0.y; accv[2] += p*v0.z; accv[3] += p*v0.w;
        accv[4] += p*v1.x; accv[5] += p*v1.y; accv[6] += p*v1.z; accv[7] += p*v1.w;
      }
    }
    const float sc = rowscale[q2];
    const int ig = (qt << 5) + q2;
    float* cp = &g_ctx[((size_t)(b*TT + ig))*EE + (h<<6) + (dx<<3)];
    *(float4*)cp     = make_float4(accv[0]*sc, accv[1]*sc, accv[2]*sc, accv[3]*sc);
    *(float4*)(cp+4) = make_float4(accv[4]*sc, accv[5]*sc, accv[6]*sc, accv[7]*sc);
  }
}

// ---------------------------------------------------------------------------
extern "C" void kernel_launch(void* const* d_in, const int* in_sizes, int n_in,
                              void* d_out, int out_size) {
  const float* x          = (const float*)d_in[0];
  const float* u          = (const float*)d_in[1];
  const unsigned char* um = (const unsigned char*)d_in[2];
  const float* wq         = (const float*)d_in[3];
  const float* wk         = (const float*)d_in[4];
  const float* wv         = (const float*)d_in[5];
  const float* wo         = (const float*)d_in[6];
  const float* bo         = (const float*)d_in[7];
  const float* wu         = (const float*)d_in[8];
  const float* bu         = (const float*)d_in[9];

  float* out  = (float*)d_out;                    // [BS,T,E]
  float* attn = out + (size_t)BSZ*TT*EE;          // [BS,H,T,T]

  qkv_kernel<<<dim3(24, 128), 256>>>(x, wq, wk, wv);

  const size_t smem = 43552u * sizeof(float);     // 174,208 B
  cudaFuncSetAttribute(attn_kernel, cudaFuncAttributeMaxDynamicSharedMemorySize, (int)smem);
  attn_kernel<<<dim3(NH, TT/BQ, BSZ), 256, smem>>>(u, um, wu, bu, attn);

  oproj_kernel<<<dim3(8, 128), 256>>>(wo, bo, out);
}

// round 2
// speedup vs baseline: 1.7621x; 1.7621x over previous
#include <cuda_runtime.h>
#include <math_constants.h>
#include <cstdint>

// Problem constants
#define BSZ 8
#define TT  1024
#define EE  512
#define NH  8
#define NCU 6
#define HDM 64

// Scratch (allocation-free rule: __device__ globals)
__device__ float g_Qhi[BSZ*NH*TT*HDM];   // holds split-tf32 hi of 8*Q
__device__ float g_Qlo[BSZ*NH*TT*HDM];
__device__ float g_Khi[BSZ*NH*TT*HDM];
__device__ float g_Klo[BSZ*NH*TT*HDM];
__device__ float g_V  [BSZ*NH*TT*HDM];
__device__ float g_ctx[BSZ*TT*EE];

// ---------------------------------------------------------------------------
// PTX helpers
// ---------------------------------------------------------------------------
__device__ __forceinline__ void ldm4(uint32_t &r0, uint32_t &r1, uint32_t &r2,
                                     uint32_t &r3, uint32_t addr) {
  asm volatile("ldmatrix.sync.aligned.m8n8.x4.shared.b16 {%0,%1,%2,%3}, [%4];"
               : "=r"(r0), "=r"(r1), "=r"(r2), "=r"(r3) : "r"(addr));
}
__device__ __forceinline__ void mma8(float* c, uint32_t a0, uint32_t a1,
                                     uint32_t a2, uint32_t a3,
                                     uint32_t b0, uint32_t b1) {
  asm volatile(
    "mma.sync.aligned.m16n8k8.row.col.f32.tf32.tf32.f32 "
    "{%0,%1,%2,%3},{%4,%5,%6,%7},{%8,%9},{%0,%1,%2,%3};"
    : "+f"(c[0]), "+f"(c[1]), "+f"(c[2]), "+f"(c[3])
    : "r"(a0), "r"(a1), "r"(a2), "r"(a3), "r"(b0), "r"(b1));
}
__device__ __forceinline__ void split_tf32(float x, float &hi, float &lo) {
  uint32_t h;
  asm("cvt.rna.tf32.f32 %0, %1;" : "=r"(h) : "f"(x));
  hi = __uint_as_float(h);
  lo = x - hi;
}

// ---------------------------------------------------------------------------
// Fused QKV projection (fp32 FFMA mainloop, near fp32 peak already).
// Epilogue: Q scaled by 8 and split to tf32 hi/lo, K split, V plain fp32.
// ---------------------------------------------------------------------------
__global__ __launch_bounds__(256) void qkv_kernel(
    const float* __restrict__ x, const float* __restrict__ wq,
    const float* __restrict__ wk, const float* __restrict__ wv) {
  __shared__ float Xs[16*68];
  __shared__ float Ws[16*68];
  const int nb = blockIdx.x;           // 0..23
  const int mb = blockIdx.y;           // 0..127
  const int mat = nb >> 3;
  const int n0 = (nb & 7) << 6;
  const int m0 = mb << 6;
  const float* W = (mat == 0) ? wq : (mat == 1) ? wk : wv;
  const int tid = threadIdx.x;
  const int tx = tid & 15, ty = tid >> 4;
  const int lm = tid >> 2;
  const int lk = (tid & 3) << 2;

  float acc[4][4];
#pragma unroll
  for (int i = 0; i < 4; i++)
#pragma unroll
    for (int j = 0; j < 4; j++) acc[i][j] = 0.f;

  for (int k0 = 0; k0 < EE; k0 += 16) {
    float4 xa = *(const float4*)&x[(m0 + lm)*EE + k0 + lk];
    float4 wa = *(const float4*)&W[(n0 + lm)*EE + k0 + lk];
    __syncthreads();
    Xs[(lk+0)*68 + lm] = xa.x; Xs[(lk+1)*68 + lm] = xa.y;
    Xs[(lk+2)*68 + lm] = xa.z; Xs[(lk+3)*68 + lm] = xa.w;
    Ws[(lk+0)*68 + lm] = wa.x; Ws[(lk+1)*68 + lm] = wa.y;
    Ws[(lk+2)*68 + lm] = wa.z; Ws[(lk+3)*68 + lm] = wa.w;
    __syncthreads();
#pragma unroll
    for (int k = 0; k < 16; k++) {
      float4 a = *(const float4*)&Xs[k*68 + (ty<<2)];
      float4 b = *(const float4*)&Ws[k*68 + (tx<<2)];
      acc[0][0] += a.x*b.x; acc[0][1] += a.x*b.y; acc[0][2] += a.x*b.z; acc[0][3] += a.x*b.w;
      acc[1][0] += a.y*b.x; acc[1][1] += a.y*b.y; acc[1][2] += a.y*b.z; acc[1][3] += a.y*b.w;
      acc[2][0] += a.z*b.x; acc[2][1] += a.z*b.y; acc[2][2] += a.z*b.z; acc[2][3] += a.z*b.w;
      acc[3][0] += a.w*b.x; acc[3][1] += a.w*b.y; acc[3][2] += a.w*b.z; acc[3][3] += a.w*b.w;
    }
  }
  const int n = n0 + (tx << 2);
  const int hh = n >> 6, d = n & 63;
#pragma unroll
  for (int ii = 0; ii < 4; ii++) {
    const int m = m0 + (ty << 2) + ii;
    const int b = m >> 10, t = m & 1023;
    const size_t off = ((size_t)((b*NH + hh)*TT) + t)*HDM + d;
    float4 v = make_float4(acc[ii][0], acc[ii][1], acc[ii][2], acc[ii][3]);
    if (mat == 2) {
      *(float4*)&g_V[off] = v;
    } else {
      if (mat == 0) { v.x *= 8.f; v.y *= 8.f; v.z *= 8.f; v.w *= 8.f; }
      float4 hi, lo;
      split_tf32(v.x, hi.x, lo.x); split_tf32(v.y, hi.y, lo.y);
      split_tf32(v.z, hi.z, lo.z); split_tf32(v.w, hi.w, lo.w);
      float* Ha = (mat == 0) ? g_Qhi : g_Khi;
      float* La = (mat == 0) ? g_Qlo : g_Klo;
      *(float4*)&Ha[off] = hi;
      *(float4*)&La[off] = lo;
    }
  }
}

// ---------------------------------------------------------------------------
// Output projection: out = ctx @ wo^T + bo  (fp32 FFMA)
// ---------------------------------------------------------------------------
__global__ __launch_bounds__(256) void oproj_kernel(
    const float* __restrict__ wo, const float* __restrict__ bo,
    float* __restrict__ out) {
  __shared__ float Xs[16*68];
  __shared__ float Ws[16*68];
  const int n0 = blockIdx.x << 6;
  const int m0 = blockIdx.y << 6;
  const int tid = threadIdx.x;
  const int tx = tid & 15, ty = tid >> 4;
  const int lm = tid >> 2;
  const int lk = (tid & 3) << 2;

  float acc[4][4];
#pragma unroll
  for (int i = 0; i < 4; i++)
#pragma unroll
    for (int j = 0; j < 4; j++) acc[i][j] = 0.f;

  for (int k0 = 0; k0 < EE; k0 += 16) {
    float4 xa = *(const float4*)&g_ctx[(m0 + lm)*EE + k0 + lk];
    float4 wa = *(const float4*)&wo[(n0 + lm)*EE + k0 + lk];
    __syncthreads();
    Xs[(lk+0)*68 + lm] = xa.x; Xs[(lk+1)*68 + lm] = xa.y;
    Xs[(lk+2)*68 + lm] = xa.z; Xs[(lk+3)*68 + lm] = xa.w;
    Ws[(lk+0)*68 + lm] = wa.x; Ws[(lk+1)*68 + lm] = wa.y;
    Ws[(lk+2)*68 + lm] = wa.z; Ws[(lk+3)*68 + lm] = wa.w;
    __syncthreads();
#pragma unroll
    for (int k = 0; k < 16; k++) {
      float4 a = *(const float4*)&Xs[k*68 + (ty<<2)];
      float4 b = *(const float4*)&Ws[k*68 + (tx<<2)];
      acc[0][0] += a.x*b.x; acc[0][1] += a.x*b.y; acc[0][2] += a.x*b.z; acc[0][3] += a.x*b.w;
      acc[1][0] += a.y*b.x; acc[1][1] += a.y*b.y; acc[1][2] += a.y*b.z; acc[1][3] += a.y*b.w;
      acc[2][0] += a.z*b.x; acc[2][1] += a.z*b.y; acc[2][2] += a.z*b.z; acc[2][3] += a.z*b.w;
      acc[3][0] += a.w*b.x; acc[3][1] += a.w*b.y; acc[3][2] += a.w*b.z; acc[3][3] += a.w*b.w;
    }
  }
  const int n = n0 + (tx << 2);
  float4 bv = *(const float4*)&bo[n];
#pragma unroll
  for (int ii = 0; ii < 4; ii++) {
    const int m = m0 + (ty << 2) + ii;
    float4 v = make_float4(acc[ii][0] + bv.x, acc[ii][1] + bv.y,
                           acc[ii][2] + bv.z, acc[ii][3] + bv.w);
    *(float4*)&out[(size_t)m*EE + n] = v;
  }
}

// ---------------------------------------------------------------------------
// Attention with tensor cores (mma.sync tf32).
// One block per (h, q-tile of 32, b). 256 threads, 8 warps.
// Phase 1 : S = (8Q)K^T via split-tf32 mma (3 MMA combos -> fp32-grade logits)
// Phase 1.5: S += ubias(u,wu,bu), mask
// Phase 2 : exact softmax over full rows (S in smem)
// Phase 3a: write attn (normalized) coalesced
// Phase 3b: ctx = P @ V via single tf32 mma
// ---------------------------------------------------------------------------
#define S_LD   1028
#define S_OFF  0
#define QH_OFF 32896
#define QL_OFF 35072
#define KH_OFF 37248
#define KL_OFF 45952
#define RS_OFF 54656
#define VS_OFF KH_OFF
#define SMEM_FLOATS 54688    // 218,752 bytes

__global__ __launch_bounds__(256, 1) void attn_kernel(
    const float* __restrict__ u, const unsigned char* __restrict__ umask,
    const float* __restrict__ wu, const float* __restrict__ bu,
    float* __restrict__ attn_out) {
  extern __shared__ float sm[];
  const int h  = blockIdx.x;
  const int qt = blockIdx.y;
  const int b  = blockIdx.z;
  const int tid = threadIdx.x;
  const int bh = b*NH + h;
  const uint32_t smb = (uint32_t)__cvta_generic_to_shared(sm);

  // ---- stage Q hi/lo tiles (32 x 64), ld 68 ----
  {
    const float* Qh = g_Qhi + (size_t)bh*TT*HDM + (size_t)qt*32*HDM;
    const float* Ql = g_Qlo + (size_t)bh*TT*HDM + (size_t)qt*32*HDM;
#pragma unroll
    for (int r = 0; r < 2; r++) {
      int id = tid + (r << 8);          // 0..511
      int i = id >> 4;
      int k4 = (id & 15) << 2;
      *(float4*)&sm[QH_OFF + i*68 + k4] = *(const float4*)&Qh[i*HDM + k4];
      *(float4*)&sm[QL_OFF + i*68 + k4] = *(const float4*)&Ql[i*HDM + k4];
    }
  }

  const int lane = tid & 31, w = tid >> 5;
  const int wm = w >> 2, wn = w & 3;    // warp grid 2(m) x 4(n)
  const int m0 = wm << 4;
  const int lr = (lane & 7) + ((lane >> 3) & 1)*8;  // ldmatrix row-in-16
  const int lc = (lane >> 4) << 2;                  // ldmatrix col 0/4
  const int gr = lane >> 2, ct = lane & 3;          // fragment coords

  const float* Kh_g = g_Khi + (size_t)bh*TT*HDM;
  const float* Kl_g = g_Klo + (size_t)bh*TT*HDM;

  // ---- Phase 1: raw scores (already x8 via Q pre-scale) ----
  const uint32_t a_qh = smb + (uint32_t)(QH_OFF + (m0 + lr)*68 + lc)*4u;
  const uint32_t a_ql = smb + (uint32_t)(QL_OFF + (m0 + lr)*68 + lc)*4u;
  const uint32_t b_h0 = smb + (uint32_t)(KH_OFF + (wn*32      + lr)*68 + lc)*4u;
  const uint32_t b_h1 = smb + (uint32_t)(KH_OFF + (wn*32 + 16 + lr)*68 + lc)*4u;
  const uint32_t b_l0 = smb + (uint32_t)(KL_OFF + (wn*32      + lr)*68 + lc)*4u;
  const uint32_t b_l1 = smb + (uint32_t)(KL_OFF + (wn*32 + 16 + lr)*68 + lc)*4u;

  for (int jt = 0; jt < 8; jt++) {
    const int j0 = jt << 7;             // 128-wide j tile
    __syncthreads();
#pragma unroll
    for (int r = 0; r < 8; r++) {       // stage K hi/lo (128 x 64)
      int id = tid + (r << 8);          // 0..2047
      int j = id >> 4;
      int k4 = (id & 15) << 2;
      *(float4*)&sm[KH_OFF + j*68 + k4] = *(const float4*)&Kh_g[(size_t)(j0 + j)*HDM + k4];
      *(float4*)&sm[KL_OFF + j*68 + k4] = *(const float4*)&Kl_g[(size_t)(j0 + j)*HDM + k4];
    }
    __syncthreads();

    float acc[4][4] = {};
#pragma unroll
    for (int kc = 0; kc < 8; kc++) {
      const uint32_t kb = (uint32_t)(kc*8*4);
      uint32_t ah0, ah1, ah2, ah3, al0, al1, al2, al3;
      ldm4(ah0, ah1, ah2, ah3, a_qh + kb);
      ldm4(al0, al1, al2, al3, a_ql + kb);
      uint32_t h00, h01, h02, h03, l00, l01, l02, l03;
      ldm4(h00, h01, h02, h03, b_h0 + kb);   // ntiles 0,1: b-pairs (r0,r2),(r1,r3)
      ldm4(l00, l01, l02, l03, b_l0 + kb);
      uint32_t h10, h11, h12, h13, l10, l11, l12, l13;
      ldm4(h10, h11, h12, h13, b_h1 + kb);   // ntiles 2,3
      ldm4(l10, l11, l12, l13, b_l1 + kb);

      // split-tf32: hi*hi + hi*lo + lo*hi
      mma8(acc[0], ah0, ah1, ah2, ah3, h00, h02);
      mma8(acc[0], ah0, ah1, ah2, ah3, l00, l02);
      mma8(acc[0], al0, al1, al2, al3, h00, h02);
      mma8(acc[1], ah0, ah1, ah2, ah3, h01, h03);
      mma8(acc[1], ah0, ah1, ah2, ah3, l01, l03);
      mma8(acc[1], al0, al1, al2, al3, h01, h03);
      mma8(acc[2], ah0, ah1, ah2, ah3, h10, h12);
      mma8(acc[2], ah0, ah1, ah2, ah3, l10, l12);
      mma8(acc[2], al0, al1, al2, al3, h10, h12);
      mma8(acc[3], ah0, ah1, ah2, ah3, h11, h13);
      mma8(acc[3], ah0, ah1, ah2, ah3, l11, l13);
      mma8(acc[3], al0, al1, al2, al3, h11, h13);
    }
    // store fragments to S
#pragma unroll
    for (int t = 0; t < 4; t++) {
      const int col = j0 + wn*32 + t*8 + 2*ct;
      *(float2*)&sm[S_OFF + (m0 + gr)*S_LD + col]     = make_float2(acc[t][0], acc[t][1]);
      *(float2*)&sm[S_OFF + (m0 + 8 + gr)*S_LD + col] = make_float2(acc[t][2], acc[t][3]);
    }
  }
  __syncthreads();

  // ---- Phase 1.5: S += ubias, mask ----
  {
    float wuh[NCU];
#pragma unroll
    for (int c = 0; c < NCU; c++) wuh[c] = wu[h*NCU + c];
    const float buh = bu[h];
    const int qy = tid >> 5, jx = tid & 31;
    for (int jt = 0; jt < 8; jt++) {
      const int j0 = jt << 7;
      float4 row4[4];
#pragma unroll
      for (int ii = 0; ii < 4; ii++) {
        const int r = (qy << 2) + ii;
        const int ig = (qt << 5) + r;
        float4 sv = *(float4*)&sm[S_OFF + r*S_LD + j0 + (jx << 2)];
        float4 bias = make_float4(buh, buh, buh, buh);
#pragma unroll
        for (int c = 0; c < NCU; c++) {
          const float4 uv = *(const float4*)&u[(((size_t)(b*NCU + c)*TT + ig) << 10) + j0 + (jx << 2)];
          bias.x += wuh[c]*uv.x; bias.y += wuh[c]*uv.y;
          bias.z += wuh[c]*uv.z; bias.w += wuh[c]*uv.w;
        }
        row4[ii] = make_float4(sv.x + bias.x, sv.y + bias.y, sv.z + bias.z, sv.w + bias.w);
      }
      const int ib = (qt << 5) + (qy << 2);
#pragma unroll
      for (int jj = 0; jj < 4; jj++) {
        const int jg = j0 + (jx << 2) + jj;
        uchar4 m4 = *(const uchar4*)&umask[((size_t)b << 20) + ((size_t)jg << 10) + ib];
        if (m4.x) ((float*)&row4[0])[jj] = -CUDART_INF_F;
        if (m4.y) ((float*)&row4[1])[jj] = -CUDART_INF_F;
        if (m4.z) ((float*)&row4[2])[jj] = -CUDART_INF_F;
        if (m4.w) ((float*)&row4[3])[jj] = -CUDART_INF_F;
      }
#pragma unroll
      for (int ii = 0; ii < 4; ii++)
        *(float4*)&sm[S_OFF + (((qy << 2) + ii))*S_LD + j0 + (jx << 2)] = row4[ii];
    }
  }
  __syncthreads();

  // ---- Phase 2: exact softmax (unnormalized exp kept in S) ----
  {
#pragma unroll
    for (int rr = 0; rr < 4; rr++) {
      const int r = (w << 2) + rr;
      float4* Sr = (float4*)&sm[S_OFF + r*S_LD];
      float mx = -CUDART_INF_F;
#pragma unroll
      for (int it = 0; it < 8; it++) {
        float4 v = Sr[lane + (it << 5)];
        mx = fmaxf(mx, fmaxf(fmaxf(v.x, v.y), fmaxf(v.z, v.w)));
      }
#pragma unroll
      for (int off = 16; off > 0; off >>= 1)
        mx = fmaxf(mx, __shfl_xor_sync(0xffffffffu, mx, off));
      float sum = 0.f;
#pragma unroll
      for (int it = 0; it < 8; it++) {
        float4 v = Sr[lane + (it << 5)];
        v.x = __expf(v.x - mx); v.y = __expf(v.y - mx);
        v.z = __expf(v.z - mx); v.w = __expf(v.w - mx);
        Sr[lane + (it << 5)] = v;
        sum += v.x + v.y + v.z + v.w;
      }
#pragma unroll
      for (int off = 16; off > 0; off >>= 1)
        sum += __shfl_xor_sync(0xffffffffu, sum, off);
      if (lane == 0) sm[RS_OFF + r] = 1.f / sum;
    }
  }
  __syncthreads();

  // ---- Phase 3a: write attn (normalized), coalesced ----
#pragma unroll 4
  for (int r = 0; r < 32; r++) {
    const float sc = sm[RS_OFF + r];
    float4 v = ((const float4*)&sm[S_OFF + r*S_LD])[tid];
    v.x *= sc; v.y *= sc; v.z *= sc; v.w *= sc;
    const size_t ig = (size_t)bh*TT + (qt << 5) + r;
    ((float4*)&attn_out[ig << 10])[tid] = v;
  }

  // ---- Phase 3b: ctx = P @ V (tf32 mma, V staged row-major ld 68) ----
  {
    const int n0w = wn << 4;            // warp covers d in [n0w, n0w+16)
    float accv[2][4] = {};
    const float* Vg = g_V + (size_t)bh*TT*HDM;
    for (int s = 0; s < 8; s++) {
      const int j0s = s << 7;
      __syncthreads();
#pragma unroll
      for (int r = 0; r < 8; r++) {
        int id = tid + (r << 8);
        int j = id >> 4;
        int k4 = (id & 15) << 2;
        *(float4*)&sm[VS_OFF + j*68 + k4] = *(const float4*)&Vg[(size_t)(j0s + j)*HDM + k4];
      }
      __syncthreads();
#pragma unroll
      for (int kc = 0; kc < 16; kc++) {
        const int k0 = kc << 3;
        uint32_t a0, a1, a2, a3;
        ldm4(a0, a1, a2, a3,
             smb + (uint32_t)(S_OFF + (m0 + lr)*S_LD + j0s + k0 + lc)*4u);
#pragma unroll
        for (int t = 0; t < 2; t++) {
          uint32_t b0 = __float_as_uint(sm[VS_OFF + (k0 + ct)*68 + n0w + t*8 + gr]);
          uint32_t b1 = __float_as_uint(sm[VS_OFF + (k0 + 4 + ct)*68 + n0w + t*8 + gr]);
          mma8(accv[t], a0, a1, a2, a3, b0, b1);
        }
      }
    }
    const float sc0 = sm[RS_OFF + m0 + gr];
    const float sc1 = sm[RS_OFF + m0 + 8 + gr];
    const size_t base = (size_t)(b*TT + (qt << 5))*EE;
#pragma unroll
    for (int t = 0; t < 2; t++) {
      const int col = (h << 6) + n0w + t*8 + 2*ct;
      *(float2*)&g_ctx[base + (size_t)(m0 + gr)*EE + col] =
          make_float2(accv[t][0]*sc0, accv[t][1]*sc0);
      *(float2*)&g_ctx[base + (size_t)(m0 + 8 + gr)*EE + col] =
          make_float2(accv[t][2]*sc1, accv[t][3]*sc1);
    }
  }
}

// ---------------------------------------------------------------------------
extern "C" void kernel_launch(void* const* d_in, const int* in_sizes, int n_in,
                              void* d_out, int out_size) {
  const float* x          = (const float*)d_in[0];
  const float* u          = (const float*)d_in[1];
  const unsigned char* um = (const unsigned char*)d_in[2];
  const float* wq         = (const float*)d_in[3];
  const float* wk         = (const float*)d_in[4];
  const float* wv         = (const float*)d_in[5];
  const float* wo         = (const float*)d_in[6];
  const float* bo         = (const float*)d_in[7];
  const float* wu         = (const float*)d_in[8];
  const float* bu         = (const float*)d_in[9];

  float* out  = (float*)d_out;                    // [BS,T,E]
  float* attn = out + (size_t)BSZ*TT*EE;          // [BS,H,T,T]

  qkv_kernel<<<dim3(24, 128), 256>>>(x, wq, wk, wv);

  const size_t smem = (size_t)SMEM_FLOATS * sizeof(float);   // 218,752 B
  cudaFuncSetAttribute(attn_kernel, cudaFuncAttributeMaxDynamicSharedMemorySize, (int)smem);
  attn_kernel<<<dim3(NH, TT/32, BSZ), 256, smem>>>(u, um, wu, bu, attn);

  oproj_kernel<<<dim3(8, 128), 256>>>(wo, bo, out);
}